// round 13
// baseline (speedup 1.0000x reference)
#include <cuda_runtime.h>
#include <cuda_bf16.h>
#include <cstdint>

// ---------------------------------------------------------------------------
// Problem constants
// ---------------------------------------------------------------------------
namespace {
constexpr int B_  = 4;
constexpr int N_  = 1024;
constexpr int T_  = 12;
constexpr int C_  = 256;
constexpr int DK_ = 32;
constexpr int M_  = B_ * N_ * T_;              // 49152 rows
constexpr size_t MC_ = (size_t)M_ * C_;        // 12,582,912 elems per tensor
constexpr float SCALE_ = 0.17677669529663687f; // 1/sqrt(DK)

// GEMM tiling (mma.sync m16n8k16 bf16), 4 warps of 64x64
constexpr int BM = 128, BN = 128, BK = 32;
constexpr int NKT = C_ / BK;                   // 8 mainloop iterations
constexpr int LDS = 40;                        // smem row stride in bf16 (80 B)

// double-buffered smem layout (bytes)
constexpr unsigned TILE_BYTES = BM * LDS * 2;        // 10240
constexpr unsigned OFF_AH = 0;
constexpr unsigned OFF_AL = 1 * TILE_BYTES;
constexpr unsigned OFF_BH = 2 * TILE_BYTES;
constexpr unsigned OFF_BL = 3 * TILE_BYTES;
constexpr unsigned STAGE_B = 4 * TILE_BYTES;         // 40960
constexpr unsigned SMEM_GEMM = 2 * STAGE_B;          // 81920

// Attention smem layout
constexpr int RS = 36;                         // row stride (floats)
constexpr int TS = 444;                        // tile stride (12*36 + 12 pad)
constexpr int PR = 13;                         // P row stride
constexpr int HEAD_SM = 5 * TS + 4 * T_ * PR;  // 2844 floats
constexpr unsigned SMEM_ATTN = 8 * HEAD_SM * 4; // 91,008 bytes
}

// ---------------------------------------------------------------------------
// Device scratch
// ---------------------------------------------------------------------------
__device__ float          g_proj[6 * MC_];      // fp32 projected Q/K/V
__device__ float          g_ctx [4 * MC_];      // fp32 attention contexts
__device__ __nv_bfloat16  g_w_h[7 * C_ * C_];   // bf16 hi of 7 weights
__device__ __nv_bfloat16  g_w_l[7 * C_ * C_];   // bf16 lo of 7 weights

// ---------------------------------------------------------------------------
// PTX helpers (baseline ISA only — no 'a'-suffix features)
// ---------------------------------------------------------------------------
__device__ __forceinline__ uint32_t cvta_s(const void* p) {
    uint32_t a;
    asm("{ .reg .u64 t; cvta.to.shared.u64 t, %1; cvt.u32.u64 %0, t; }"
        : "=r"(a) : "l"(p));
    return a;
}
__device__ __forceinline__ void ldsm4(uint32_t* r, uint32_t addr) {
    asm volatile("ldmatrix.sync.aligned.m8n8.x4.shared.b16 {%0,%1,%2,%3}, [%4];"
                 : "=r"(r[0]), "=r"(r[1]), "=r"(r[2]), "=r"(r[3]) : "r"(addr));
}
__device__ __forceinline__ void mma_bf16(float* d, const uint32_t* a,
                                         const uint32_t* b) {
    asm volatile(
        "mma.sync.aligned.m16n8k16.row.col.f32.bf16.bf16.f32 "
        "{%0,%1,%2,%3}, {%4,%5,%6,%7}, {%8,%9}, {%0,%1,%2,%3};"
        : "+f"(d[0]), "+f"(d[1]), "+f"(d[2]), "+f"(d[3])
        : "r"(a[0]), "r"(a[1]), "r"(a[2]), "r"(a[3]), "r"(b[0]), "r"(b[1]));
}
__device__ __forceinline__ uint32_t pack_bf2(float a, float b) {
    __nv_bfloat162 t = __floats2bfloat162_rn(a, b);
    return *reinterpret_cast<uint32_t*>(&t);
}
__device__ __forceinline__ void cp16(uint32_t dst, const void* src) {
    asm volatile("cp.async.cg.shared.global [%0], [%1], 16;"
                 :: "r"(dst), "l"(src) : "memory");
}
__device__ __forceinline__ void cp_commit() {
    asm volatile("cp.async.commit_group;" ::: "memory");
}
__device__ __forceinline__ void cp_wait0() {
    asm volatile("cp.async.wait_group 0;" ::: "memory");
}

// ---------------------------------------------------------------------------
// Weight fp32 -> bf16 hi/lo split (7 weights, 256x256 each; tiny)
// ---------------------------------------------------------------------------
__global__ __launch_bounds__(256) void k_cvt_w(
    const float* __restrict__ w0, const float* __restrict__ w1,
    const float* __restrict__ w2, const float* __restrict__ w3,
    const float* __restrict__ w4, const float* __restrict__ w5,
    const float* __restrict__ w6)
{
    const int z = blockIdx.y;
    const float* s;
    if      (z == 0) s = w0;
    else if (z == 1) s = w1;
    else if (z == 2) s = w2;
    else if (z == 3) s = w3;
    else if (z == 4) s = w4;
    else if (z == 5) s = w5;
    else             s = w6;
    const size_t i = (size_t)blockIdx.x * blockDim.x + threadIdx.x; // float4 idx
    const size_t n4 = (size_t)C_ * C_ / 4;
    if (i >= n4) return;
    float4 v = ((const float4*)s)[i];
    float h0 = __bfloat162float(__float2bfloat16(v.x));
    float h1 = __bfloat162float(__float2bfloat16(v.y));
    float h2 = __bfloat162float(__float2bfloat16(v.z));
    float h3 = __bfloat162float(__float2bfloat16(v.w));
    uint32_t* hp = (uint32_t*)(g_w_h + (size_t)z * C_ * C_) + 2 * i;
    uint32_t* lp = (uint32_t*)(g_w_l + (size_t)z * C_ * C_) + 2 * i;
    hp[0] = pack_bf2(h0, h1);
    hp[1] = pack_bf2(h2, h3);
    lp[0] = pack_bf2(v.x - h0, v.y - h1);
    lp[1] = pack_bf2(v.z - h2, v.w - h3);
}

// ---------------------------------------------------------------------------
// 3-term bf16 mma.sync GEMM, 4 warps of 64x64, double-buffered, B cp.async:
//   Y[m,n] = sum_c X[m,c] * W[n,c]  (+ bias)
// 128 threads, warps in 2(m) x 2(n), warp tile 64x64, m16n8k16.
// A redundancy 2x (was 4x) -> ldsm smem traffic -33%.
// ---------------------------------------------------------------------------
template <bool HAS_BIAS>
__device__ __forceinline__ void mma_gemm(
    const float* __restrict__ X,
    const __nv_bfloat16* __restrict__ Wh, const __nv_bfloat16* __restrict__ Wl,
    const float* __restrict__ bias, float* __restrict__ Y)
{
    extern __shared__ __align__(16) char smg[];

    const int tid  = threadIdx.x;
    const int lane = tid & 31;
    const int wid  = tid >> 5;          // 0..3
    const int wm   = (wid >> 1) * 64;   // warp m offset
    const int wn   = (wid & 1) * 64;    // warp n offset
    const int m0 = blockIdx.y * BM;
    const int n0 = blockIdx.x * BN;

    const uint32_t sb = cvta_s(smg);

    // ldmatrix per-lane byte offsets (relative to tile base)
    uint32_t aoff[4][2], boff[4][2];
    {
        const int ra = wm + (lane & 7) + ((lane >> 3) & 1) * 8;
        const int ca = (lane >> 4) * 8;
#pragma unroll
        for (int im = 0; im < 4; ++im)
#pragma unroll
            for (int ks = 0; ks < 2; ++ks)
                aoff[im][ks] = (uint32_t)(((ra + im * 16) * LDS + ca + ks * 16) * 2);
        const int rb = wn + (lane & 7) + (lane >> 4) * 8;
        const int cb = ((lane >> 3) & 1) * 8;
#pragma unroll
        for (int ip = 0; ip < 4; ++ip)
#pragma unroll
            for (int ks = 0; ks < 2; ++ks)
                boff[ip][ks] = (uint32_t)(((rb + ip * 16) * LDS + cb + ks * 16) * 2);
    }

    float acc[4][8][4];
#pragma unroll
    for (int im = 0; im < 4; ++im)
#pragma unroll
        for (int in = 0; in < 8; ++in)
#pragma unroll
            for (int q = 0; q < 4; ++q) acc[im][in][q] = 0.f;

    // loader mapping: 1 thread per row, 32 k-columns each
    const int lrow = tid;               // 0..127
    const float* xg = X + (size_t)(m0 + lrow) * C_;
    const __nv_bfloat16* whg = Wh + (size_t)(n0 + lrow) * C_;
    const __nv_bfloat16* wlg = Wl + (size_t)(n0 + lrow) * C_;
    const unsigned toff = (unsigned)(lrow * LDS * 2);   // 80 B per row

    float4 xv[8];

    auto fetch_a = [&](int kt) {
        const float4* xp = (const float4*)(xg + kt * BK);
#pragma unroll
        for (int q = 0; q < 8; ++q) xv[q] = xp[q];
    };
    auto cp_b = [&](int kt, int s) {
        const uint32_t so = sb + s * STAGE_B;
        const __nv_bfloat16* wh = whg + kt * BK;
        const __nv_bfloat16* wl = wlg + kt * BK;
        cp16(so + OFF_BH + toff,      wh);
        cp16(so + OFF_BH + toff + 16, wh + 8);
        cp16(so + OFF_BH + toff + 32, wh + 16);
        cp16(so + OFF_BH + toff + 48, wh + 24);
        cp16(so + OFF_BL + toff,      wl);
        cp16(so + OFF_BL + toff + 16, wl + 8);
        cp16(so + OFF_BL + toff + 32, wl + 16);
        cp16(so + OFF_BL + toff + 48, wl + 24);
        cp_commit();
    };
    auto store_a = [&](int s) {
        char* sp = smg + s * STAGE_B;
        uint32_t hh[16], ll[16];
#pragma unroll
        for (int q = 0; q < 8; ++q) {
            const float4 v = xv[q];
            float h0 = __bfloat162float(__float2bfloat16(v.x));
            float h1 = __bfloat162float(__float2bfloat16(v.y));
            float h2 = __bfloat162float(__float2bfloat16(v.z));
            float h3 = __bfloat162float(__float2bfloat16(v.w));
            hh[q * 2 + 0] = pack_bf2(h0, h1);
            hh[q * 2 + 1] = pack_bf2(h2, h3);
            ll[q * 2 + 0] = pack_bf2(v.x - h0, v.y - h1);
            ll[q * 2 + 1] = pack_bf2(v.z - h2, v.w - h3);
        }
        uint4* dAh = (uint4*)(sp + OFF_AH + toff);
        uint4* dAl = (uint4*)(sp + OFF_AL + toff);
#pragma unroll
        for (int q = 0; q < 4; ++q) {
            dAh[q] = make_uint4(hh[4 * q], hh[4 * q + 1], hh[4 * q + 2], hh[4 * q + 3]);
            dAl[q] = make_uint4(ll[4 * q], ll[4 * q + 1], ll[4 * q + 2], ll[4 * q + 3]);
        }
    };

    // prologue: tile 0 into stage 0
    cp_b(0, 0);
    fetch_a(0);
    store_a(0);
    cp_wait0();
    __syncthreads();

#pragma unroll 1
    for (int kt = 0; kt < NKT; ++kt) {
        const int cur = kt & 1;
        if (kt < NKT - 1) {
            cp_b(kt + 1, cur ^ 1);     // async B copy into other stage
            fetch_a(kt + 1);           // fp32 A LDG in flight, covered by MMAs
        }

        const uint32_t so = sb + cur * STAGE_B;
#pragma unroll
        for (int ks = 0; ks < 2; ++ks) {
            // term 1: hi * w_hi
            uint32_t ah[4][4], bh[4][4];
#pragma unroll
            for (int im = 0; im < 4; ++im) ldsm4(ah[im], so + OFF_AH + aoff[im][ks]);
#pragma unroll
            for (int ip = 0; ip < 4; ++ip) ldsm4(bh[ip], so + OFF_BH + boff[ip][ks]);
#pragma unroll
            for (int im = 0; im < 4; ++im)
#pragma unroll
                for (int in = 0; in < 8; ++in)
                    mma_bf16(acc[im][in], ah[im], &bh[in >> 1][(in & 1) * 2]);

            // term 2: lo * w_hi  (bh still live)
            uint32_t al[4][4];
#pragma unroll
            for (int im = 0; im < 4; ++im) ldsm4(al[im], so + OFF_AL + aoff[im][ks]);
#pragma unroll
            for (int im = 0; im < 4; ++im)
#pragma unroll
                for (int in = 0; in < 8; ++in)
                    mma_bf16(acc[im][in], al[im], &bh[in >> 1][(in & 1) * 2]);

            // term 3: hi * w_lo  (ah still live, bh dead)
            uint32_t bl[4][4];
#pragma unroll
            for (int ip = 0; ip < 4; ++ip) ldsm4(bl[ip], so + OFF_BL + boff[ip][ks]);
#pragma unroll
            for (int im = 0; im < 4; ++im)
#pragma unroll
                for (int in = 0; in < 8; ++in)
                    mma_bf16(acc[im][in], ah[im], &bl[in >> 1][(in & 1) * 2]);
        }

        if (kt < NKT - 1) store_a(cur ^ 1);
        cp_wait0();
        __syncthreads();
    }

    // epilogue
    const int er = lane >> 2;
    const int ec = (lane & 3) * 2;
#pragma unroll
    for (int im = 0; im < 4; ++im) {
#pragma unroll
        for (int in = 0; in < 8; ++in) {
            const int row = m0 + wm + im * 16 + er;
            const int col = n0 + wn + in * 8 + ec;
            float b0 = 0.f, b1 = 0.f;
            if (HAS_BIAS) { b0 = bias[col]; b1 = bias[col + 1]; }
            float2 v0 = make_float2(acc[im][in][0] + b0, acc[im][in][1] + b1);
            float2 v1 = make_float2(acc[im][in][2] + b0, acc[im][in][3] + b1);
            *(float2*)&Y[(size_t)row * C_ + col]       = v0;
            *(float2*)&Y[(size_t)(row + 8) * C_ + col] = v1;
        }
    }
}

__global__ __launch_bounds__(128, 2) void k_mma_proj(
    const float* __restrict__ x0, const float* __restrict__ x1,
    const float* __restrict__ x2, const float* __restrict__ x3,
    const float* __restrict__ x4, const float* __restrict__ x5)
{
    const int z = blockIdx.z;
    const float* X;
    if      (z == 0) X = x0;
    else if (z == 1) X = x1;
    else if (z == 2) X = x2;
    else if (z == 3) X = x3;
    else if (z == 4) X = x4;
    else             X = x5;
    mma_gemm<false>(X, g_w_h + (size_t)z * C_ * C_, g_w_l + (size_t)z * C_ * C_,
                    nullptr, g_proj + (size_t)z * MC_);
}

__global__ __launch_bounds__(128, 2) void k_mma_out(
    const float* __restrict__ bias, float* __restrict__ out)
{
    const int z = blockIdx.z;
    mma_gemm<true>(g_ctx + (size_t)z * MC_,
                   g_w_h + (size_t)6 * C_ * C_, g_w_l + (size_t)6 * C_ * C_,
                   bias, out + (size_t)z * MC_);
}

// ---------------------------------------------------------------------------
// Fused 4-way temporal attention, shuffle-free smem version (unchanged).
// ---------------------------------------------------------------------------
__device__ __forceinline__ void attn_row(
    const float* __restrict__ A, const float* __restrict__ Bt,
    float* __restrict__ Prow, int t)
{
    float4 ar[8];
    const float4* ap = (const float4*)(A + t * RS);
#pragma unroll
    for (int q = 0; q < 8; ++q) ar[q] = ap[q];

    float s[T_];
#pragma unroll
    for (int j = 0; j < T_; ++j) {
        const float4* bp = (const float4*)(Bt + j * RS);
        float acc = 0.f;
#pragma unroll
        for (int q = 0; q < 8; ++q) {
            float4 b = bp[q];
            acc += ar[q].x * b.x + ar[q].y * b.y + ar[q].z * b.z + ar[q].w * b.w;
        }
        s[j] = acc;
    }
    float mx = s[0];
#pragma unroll
    for (int j = 1; j < T_; ++j) mx = fmaxf(mx, s[j]);
    float e[T_];
    float sum = 0.f;
#pragma unroll
    for (int j = 0; j < T_; ++j) { e[j] = __expf((s[j] - mx) * SCALE_); sum += e[j]; }
    const float inv = 1.0f / sum;
#pragma unroll
    for (int j = 0; j < T_; ++j) Prow[j] = e[j] * inv;
}

__global__ __launch_bounds__(256) void k_attn(
    const float* __restrict__ kj, const float* __restrict__ vfs)
{
    extern __shared__ float sm[];
    const int bn = blockIdx.x;
    const int h  = threadIdx.x >> 5;
    const int d  = threadIdx.x & 31;

    float* hs   = sm + h * HEAD_SM;
    float* tQf  = hs;
    float* tKf  = hs + 1 * TS;
    float* tQs  = hs + 2 * TS;
    float* tKs  = hs + 3 * TS;
    float* tQfs = hs + 4 * TS;
    float* P    = hs + 5 * TS;      // [4][12][PR]

    const size_t base = (size_t)bn * T_ * C_ + h * DK_ + d;

    const float* Qf = g_proj + 0 * MC_;
    const float* Kf = g_proj + 1 * MC_;
    const float* Vf = g_proj + 2 * MC_;
    const float* Qs = g_proj + 3 * MC_;
    const float* Ks = g_proj + 4 * MC_;
    const float* Vs = g_proj + 5 * MC_;

    float vf[T_], vs[T_];
#pragma unroll
    for (int t = 0; t < T_; ++t) {
        const size_t o = base + (size_t)t * C_;
        const float qf = Qf[o];
        const float kf = Kf[o];
        const float qs = Qs[o];
        const float ks = Ks[o];
        vf[t] = Vf[o];
        vs[t] = Vs[o];
        const float den = vfs[t] + 1e-5f;
        const float qfsv = kj[t] * (qs - qs * qs / den);
        tQf [t * RS + d] = qf;
        tKf [t * RS + d] = kf;
        tQs [t * RS + d] = qs;
        tKs [t * RS + d] = ks;
        tQfs[t * RS + d] = qfsv;
    }
    __syncwarp();

    {
        const int a0 = d / T_;          // 0..2
        const int t0 = d - a0 * T_;
        const float* Asel[4] = {tQf, tKf, tKs, tQs};
        const float* Bsel[4] = {tKf, tQfs, tQf, tKs};
        attn_row(Asel[a0], Bsel[a0], P + (a0 * T_ + t0) * PR, t0);
        if (d < 16) {
            const int r  = 32 + d;
            const int a1 = r / T_;      // 2..3
            const int t1 = r - a1 * T_;
            attn_row(Asel[a1], Bsel[a1], P + (a1 * T_ + t1) * PR, t1);
        }
    }
    __syncwarp();

#pragma unroll
    for (int a = 0; a < 4; ++a) {
        const float* vv = (a < 2) ? vf : vs;
        float* outp = g_ctx + (size_t)a * MC_ + base;
#pragma unroll
        for (int t = 0; t < T_; ++t) {
            const float* pr = P + (a * T_ + t) * PR;
            float acc = 0.f;
#pragma unroll
            for (int j = 0; j < T_; ++j) acc += pr[j] * vv[j];
            outp[(size_t)t * C_] = acc;
        }
    }
}

// ---------------------------------------------------------------------------
// Entry point
// ---------------------------------------------------------------------------
extern "C" void kernel_launch(void* const* d_in, const int* /*in_sizes*/,
                              int /*n_in*/, void* d_out, int /*out_size*/)
{
    const float* flow_q  = (const float*)d_in[0];
    const float* flow_k  = (const float*)d_in[1];
    const float* flow_v  = (const float*)d_in[2];
    const float* speed_q = (const float*)d_in[3];
    const float* speed_k = (const float*)d_in[4];
    const float* speed_v = (const float*)d_in[5];
    const float* w_fq  = (const float*)d_in[6];
    const float* w_fk  = (const float*)d_in[7];
    const float* w_fv  = (const float*)d_in[8];
    const float* w_sq  = (const float*)d_in[9];
    const float* w_sk  = (const float*)d_in[10];
    const float* w_sv  = (const float*)d_in[11];
    const float* w_out = (const float*)d_in[12];
    const float* b_out = (const float*)d_in[13];
    const float* kj    = (const float*)d_in[14];
    const float* vf_fs = (const float*)d_in[15];

    cudaFuncSetAttribute(k_attn, cudaFuncAttributeMaxDynamicSharedMemorySize,
                         SMEM_ATTN);
    cudaFuncSetAttribute(k_mma_proj, cudaFuncAttributeMaxDynamicSharedMemorySize,
                         SMEM_GEMM);
    cudaFuncSetAttribute(k_mma_out, cudaFuncAttributeMaxDynamicSharedMemorySize,
                         SMEM_GEMM);

    // 1. weight fp32 -> bf16 hi/lo (tiny)
    dim3 gcw((unsigned)(C_ * C_ / 4 / 256), 7);
    k_cvt_w<<<gcw, 256>>>(w_fq, w_fk, w_fv, w_sq, w_sk, w_sv, w_out);

    // 2. six input projections (64x64 warp tiles, 2 CTAs/SM)
    dim3 gp(C_ / BN, M_ / BM, 6);   // (2, 384, 6)
    k_mma_proj<<<gp, 128, SMEM_GEMM>>>(flow_q, flow_k, flow_v,
                                       speed_q, speed_k, speed_v);

    // 3. fused attention (shuffle-free)
    k_attn<<<B_ * N_, 256, SMEM_ATTN>>>(kj, vf_fs);

    // 4. four output projections (64x64 warp tiles, 2 CTAs/SM)
    dim3 go(C_ / BN, M_ / BM, 4);   // (2, 384, 4)
    k_mma_out<<<go, 128, SMEM_GEMM>>>(b_out, (float*)d_out);
}

// round 14
// speedup vs baseline: 1.1820x; 1.1820x over previous
#include <cuda_runtime.h>
#include <cuda_bf16.h>
#include <cstdint>

// ---------------------------------------------------------------------------
// Problem constants
// ---------------------------------------------------------------------------
namespace {
constexpr int B_  = 4;
constexpr int N_  = 1024;
constexpr int T_  = 12;
constexpr int C_  = 256;
constexpr int DK_ = 32;
constexpr int M_  = B_ * N_ * T_;              // 49152 rows
constexpr size_t MC_ = (size_t)M_ * C_;        // 12,582,912 elems per tensor
constexpr float SCALE_ = 0.17677669529663687f; // 1/sqrt(DK)

// GEMM tiling (mma.sync m16n8k16 bf16) — R12 config: 8 warps of 64x32
constexpr int BM = 128, BN = 128, BK = 32;
constexpr int NKT = C_ / BK;                   // 8 mainloop iterations
constexpr int LDS = 40;                        // smem row stride in bf16 (80 B)

// double-buffered smem layout (bytes)
constexpr unsigned TILE_BYTES = BM * LDS * 2;        // 10240
constexpr unsigned OFF_AH = 0;
constexpr unsigned OFF_AL = 1 * TILE_BYTES;
constexpr unsigned OFF_BH = 2 * TILE_BYTES;
constexpr unsigned OFF_BL = 3 * TILE_BYTES;
constexpr unsigned STAGE_B = 4 * TILE_BYTES;         // 40960
constexpr unsigned SMEM_GEMM = 2 * STAGE_B;          // 81920

// Attention smem layout
constexpr int RS = 36;                         // row stride (floats)
constexpr int TS = 444;                        // tile stride (12*36 + 12 pad)
constexpr int PR = 13;                         // P row stride
constexpr int HEAD_SM = 5 * TS + 4 * T_ * PR;  // 2844 floats
constexpr unsigned SMEM_ATTN = 8 * HEAD_SM * 4; // 91,008 bytes
}

// ---------------------------------------------------------------------------
// Device scratch
// ---------------------------------------------------------------------------
__device__ float          g_proj[6 * MC_];       // fp32 projected Q/K/V
__device__ __nv_bfloat16  g_ctx_h[4 * MC_];      // bf16 hi of 4 contexts
__device__ __nv_bfloat16  g_ctx_l[4 * MC_];      // bf16 lo of 4 contexts
__device__ __nv_bfloat16  g_w_h[7 * C_ * C_];    // bf16 hi of 7 weights
__device__ __nv_bfloat16  g_w_l[7 * C_ * C_];    // bf16 lo of 7 weights

// ---------------------------------------------------------------------------
// PTX helpers (baseline ISA only — no 'a'-suffix features)
// ---------------------------------------------------------------------------
__device__ __forceinline__ uint32_t cvta_s(const void* p) {
    uint32_t a;
    asm("{ .reg .u64 t; cvta.to.shared.u64 t, %1; cvt.u32.u64 %0, t; }"
        : "=r"(a) : "l"(p));
    return a;
}
__device__ __forceinline__ void ldsm4(uint32_t* r, uint32_t addr) {
    asm volatile("ldmatrix.sync.aligned.m8n8.x4.shared.b16 {%0,%1,%2,%3}, [%4];"
                 : "=r"(r[0]), "=r"(r[1]), "=r"(r[2]), "=r"(r[3]) : "r"(addr));
}
__device__ __forceinline__ void mma_bf16(float* d, const uint32_t* a,
                                         const uint32_t* b) {
    asm volatile(
        "mma.sync.aligned.m16n8k16.row.col.f32.bf16.bf16.f32 "
        "{%0,%1,%2,%3}, {%4,%5,%6,%7}, {%8,%9}, {%0,%1,%2,%3};"
        : "+f"(d[0]), "+f"(d[1]), "+f"(d[2]), "+f"(d[3])
        : "r"(a[0]), "r"(a[1]), "r"(a[2]), "r"(a[3]), "r"(b[0]), "r"(b[1]));
}
__device__ __forceinline__ uint32_t pack_bf2(float a, float b) {
    __nv_bfloat162 t = __floats2bfloat162_rn(a, b);
    return *reinterpret_cast<uint32_t*>(&t);
}
__device__ __forceinline__ void cp16(uint32_t dst, const void* src) {
    asm volatile("cp.async.cg.shared.global [%0], [%1], 16;"
                 :: "r"(dst), "l"(src) : "memory");
}
__device__ __forceinline__ void cp_commit() {
    asm volatile("cp.async.commit_group;" ::: "memory");
}
__device__ __forceinline__ void cp_wait0() {
    asm volatile("cp.async.wait_group 0;" ::: "memory");
}

// ---------------------------------------------------------------------------
// Weight fp32 -> bf16 hi/lo split (7 weights, 256x256 each; tiny)
// ---------------------------------------------------------------------------
__global__ __launch_bounds__(256) void k_cvt_w(
    const float* __restrict__ w0, const float* __restrict__ w1,
    const float* __restrict__ w2, const float* __restrict__ w3,
    const float* __restrict__ w4, const float* __restrict__ w5,
    const float* __restrict__ w6)
{
    const int z = blockIdx.y;
    const float* s;
    if      (z == 0) s = w0;
    else if (z == 1) s = w1;
    else if (z == 2) s = w2;
    else if (z == 3) s = w3;
    else if (z == 4) s = w4;
    else if (z == 5) s = w5;
    else             s = w6;
    const size_t i = (size_t)blockIdx.x * blockDim.x + threadIdx.x; // float4 idx
    const size_t n4 = (size_t)C_ * C_ / 4;
    if (i >= n4) return;
    float4 v = ((const float4*)s)[i];
    float h0 = __bfloat162float(__float2bfloat16(v.x));
    float h1 = __bfloat162float(__float2bfloat16(v.y));
    float h2 = __bfloat162float(__float2bfloat16(v.z));
    float h3 = __bfloat162float(__float2bfloat16(v.w));
    uint32_t* hp = (uint32_t*)(g_w_h + (size_t)z * C_ * C_) + 2 * i;
    uint32_t* lp = (uint32_t*)(g_w_l + (size_t)z * C_ * C_) + 2 * i;
    hp[0] = pack_bf2(h0, h1);
    hp[1] = pack_bf2(h2, h3);
    lp[0] = pack_bf2(v.x - h0, v.y - h1);
    lp[1] = pack_bf2(v.z - h2, v.w - h3);
}

// ---------------------------------------------------------------------------
// Shared GEMM pieces (R12 config: 256 thr, 8 warps in 2(m) x 4(n), 64x32/warp)
// ---------------------------------------------------------------------------
struct GemmCtx {
    int lane, wid, wm, wn, m0, n0;
    uint32_t sb;
    uint32_t aoff[4][2], boff[2][2];
    const int tid;
    __device__ GemmCtx(uint32_t sbase) : tid(threadIdx.x), sb(sbase) {
        lane = tid & 31;
        wid  = tid >> 5;
        wm   = (wid >> 2) * 64;
        wn   = (wid & 3) * 32;
        m0 = blockIdx.y * BM;
        n0 = blockIdx.x * BN;
        const int ra = wm + (lane & 7) + ((lane >> 3) & 1) * 8;
        const int ca = (lane >> 4) * 8;
#pragma unroll
        for (int im = 0; im < 4; ++im)
#pragma unroll
            for (int ks = 0; ks < 2; ++ks)
                aoff[im][ks] = (uint32_t)(((ra + im * 16) * LDS + ca + ks * 16) * 2);
        const int rb = wn + (lane & 7) + (lane >> 4) * 8;
        const int cb = ((lane >> 3) & 1) * 8;
#pragma unroll
        for (int ip = 0; ip < 2; ++ip)
#pragma unroll
            for (int ks = 0; ks < 2; ++ks)
                boff[ip][ks] = (uint32_t)(((rb + ip * 16) * LDS + cb + ks * 16) * 2);
    }
};

__device__ __forceinline__ void mma_phase(const GemmCtx& g, uint32_t so,
                                          float acc[4][4][4])
{
#pragma unroll
    for (int ks = 0; ks < 2; ++ks) {
        uint32_t ah[4][4], al[4][4], bh[2][4], bl[2][4];
#pragma unroll
        for (int im = 0; im < 4; ++im) {
            ldsm4(ah[im], so + OFF_AH + g.aoff[im][ks]);
            ldsm4(al[im], so + OFF_AL + g.aoff[im][ks]);
        }
#pragma unroll
        for (int ip = 0; ip < 2; ++ip) {
            ldsm4(bh[ip], so + OFF_BH + g.boff[ip][ks]);
            ldsm4(bl[ip], so + OFF_BL + g.boff[ip][ks]);
        }
#pragma unroll
        for (int im = 0; im < 4; ++im) {
#pragma unroll
            for (int in = 0; in < 4; ++in) {
                const uint32_t* bph = &bh[in >> 1][(in & 1) * 2];
                const uint32_t* bpl = &bl[in >> 1][(in & 1) * 2];
                mma_bf16(acc[im][in], ah[im], bph);  // hi * w_hi
                mma_bf16(acc[im][in], ah[im], bpl);  // hi * w_lo
                mma_bf16(acc[im][in], al[im], bph);  // lo * w_hi
            }
        }
    }
}

template <bool HAS_BIAS>
__device__ __forceinline__ void epilogue(const GemmCtx& g, float acc[4][4][4],
                                         const float* __restrict__ bias,
                                         float* __restrict__ Y)
{
    const int er = g.lane >> 2;
    const int ec = (g.lane & 3) * 2;
#pragma unroll
    for (int im = 0; im < 4; ++im) {
#pragma unroll
        for (int in = 0; in < 4; ++in) {
            const int row = g.m0 + g.wm + im * 16 + er;
            const int col = g.n0 + g.wn + in * 8 + ec;
            float b0 = 0.f, b1 = 0.f;
            if (HAS_BIAS) { b0 = bias[col]; b1 = bias[col + 1]; }
            float2 v0 = make_float2(acc[im][in][0] + b0, acc[im][in][1] + b1);
            float2 v1 = make_float2(acc[im][in][2] + b0, acc[im][in][3] + b1);
            *(float2*)&Y[(size_t)row * C_ + col]       = v0;
            *(float2*)&Y[(size_t)(row + 8) * C_ + col] = v1;
        }
    }
}

// ---------------------------------------------------------------------------
// Proj GEMM (A fp32 in gmem, split fused in loader; B pre-split, cp.async)
// — exact R12 structure.
// ---------------------------------------------------------------------------
__global__ __launch_bounds__(256, 2) void k_mma_proj(
    const float* __restrict__ x0, const float* __restrict__ x1,
    const float* __restrict__ x2, const float* __restrict__ x3,
    const float* __restrict__ x4, const float* __restrict__ x5)
{
    extern __shared__ __align__(16) char smg[];
    const int z = blockIdx.z;
    const float* X;
    if      (z == 0) X = x0;
    else if (z == 1) X = x1;
    else if (z == 2) X = x2;
    else if (z == 3) X = x3;
    else if (z == 4) X = x4;
    else             X = x5;
    const __nv_bfloat16* Wh = g_w_h + (size_t)z * C_ * C_;
    const __nv_bfloat16* Wl = g_w_l + (size_t)z * C_ * C_;
    float* Y = g_proj + (size_t)z * MC_;

    GemmCtx g(cvta_s(smg));

    float acc[4][4][4];
#pragma unroll
    for (int im = 0; im < 4; ++im)
#pragma unroll
        for (int in = 0; in < 4; ++in)
#pragma unroll
            for (int q = 0; q < 4; ++q) acc[im][in][q] = 0.f;

    const int lrow = g.tid >> 1;
    const int lh   = g.tid & 1;
    const float* xg = X + (size_t)(g.m0 + lrow) * C_ + lh * 16;
    const __nv_bfloat16* whg = Wh + (size_t)(g.n0 + lrow) * C_ + lh * 16;
    const __nv_bfloat16* wlg = Wl + (size_t)(g.n0 + lrow) * C_ + lh * 16;
    const unsigned toff = (unsigned)((lrow * LDS + lh * 16) * 2);

    float4 xv[4];
    auto fetch_a = [&](int kt) {
        const float4* xp = (const float4*)(xg + kt * BK);
        xv[0] = xp[0]; xv[1] = xp[1]; xv[2] = xp[2]; xv[3] = xp[3];
    };
    auto cp_b = [&](int kt, int s) {
        const uint32_t so = g.sb + s * STAGE_B;
        cp16(so + OFF_BH + toff,      whg + kt * BK);
        cp16(so + OFF_BH + toff + 16, whg + kt * BK + 8);
        cp16(so + OFF_BL + toff,      wlg + kt * BK);
        cp16(so + OFF_BL + toff + 16, wlg + kt * BK + 8);
        cp_commit();
    };
    auto store_a = [&](int s) {
        char* sp = smg + s * STAGE_B;
        uint32_t hh[8], ll[8];
#pragma unroll
        for (int q = 0; q < 4; ++q) {
            const float4 v = xv[q];
            float h0 = __bfloat162float(__float2bfloat16(v.x));
            float h1 = __bfloat162float(__float2bfloat16(v.y));
            float h2 = __bfloat162float(__float2bfloat16(v.z));
            float h3 = __bfloat162float(__float2bfloat16(v.w));
            hh[q * 2 + 0] = pack_bf2(h0, h1);
            hh[q * 2 + 1] = pack_bf2(h2, h3);
            ll[q * 2 + 0] = pack_bf2(v.x - h0, v.y - h1);
            ll[q * 2 + 1] = pack_bf2(v.z - h2, v.w - h3);
        }
        uint4* dAh = (uint4*)(sp + OFF_AH + toff);
        uint4* dAl = (uint4*)(sp + OFF_AL + toff);
        dAh[0] = make_uint4(hh[0], hh[1], hh[2], hh[3]);
        dAh[1] = make_uint4(hh[4], hh[5], hh[6], hh[7]);
        dAl[0] = make_uint4(ll[0], ll[1], ll[2], ll[3]);
        dAl[1] = make_uint4(ll[4], ll[5], ll[6], ll[7]);
    };

    cp_b(0, 0);
    fetch_a(0);
    store_a(0);
    cp_wait0();
    __syncthreads();

#pragma unroll 1
    for (int kt = 0; kt < NKT; ++kt) {
        const int cur = kt & 1;
        if (kt < NKT - 1) {
            cp_b(kt + 1, cur ^ 1);
            fetch_a(kt + 1);
        }
        mma_phase(g, g.sb + cur * STAGE_B, acc);
        if (kt < NKT - 1) store_a(cur ^ 1);
        cp_wait0();
        __syncthreads();
    }

    epilogue<false>(g, acc, nullptr, Y);
}

// ---------------------------------------------------------------------------
// Out GEMM (A pre-split bf16 in gmem — all four tiles via cp.async)
// ---------------------------------------------------------------------------
__global__ __launch_bounds__(256, 2) void k_mma_out(
    const float* __restrict__ bias, float* __restrict__ out)
{
    extern __shared__ __align__(16) char smg[];
    const int z = blockIdx.z;
    const __nv_bfloat16* Ah = g_ctx_h + (size_t)z * MC_;
    const __nv_bfloat16* Al = g_ctx_l + (size_t)z * MC_;
    const __nv_bfloat16* Wh = g_w_h + (size_t)6 * C_ * C_;
    const __nv_bfloat16* Wl = g_w_l + (size_t)6 * C_ * C_;
    float* Y = out + (size_t)z * MC_;

    GemmCtx g(cvta_s(smg));

    float acc[4][4][4];
#pragma unroll
    for (int im = 0; im < 4; ++im)
#pragma unroll
        for (int in = 0; in < 4; ++in)
#pragma unroll
            for (int q = 0; q < 4; ++q) acc[im][in][q] = 0.f;

    const int lrow = g.tid >> 1;
    const int lh   = g.tid & 1;
    const __nv_bfloat16* ahg = Ah + (size_t)(g.m0 + lrow) * C_ + lh * 16;
    const __nv_bfloat16* alg = Al + (size_t)(g.m0 + lrow) * C_ + lh * 16;
    const __nv_bfloat16* whg = Wh + (size_t)(g.n0 + lrow) * C_ + lh * 16;
    const __nv_bfloat16* wlg = Wl + (size_t)(g.n0 + lrow) * C_ + lh * 16;
    const unsigned toff = (unsigned)((lrow * LDS + lh * 16) * 2);

    auto cp_all = [&](int kt, int s) {
        const uint32_t so = g.sb + s * STAGE_B;
        cp16(so + OFF_AH + toff,      ahg + kt * BK);
        cp16(so + OFF_AH + toff + 16, ahg + kt * BK + 8);
        cp16(so + OFF_AL + toff,      alg + kt * BK);
        cp16(so + OFF_AL + toff + 16, alg + kt * BK + 8);
        cp16(so + OFF_BH + toff,      whg + kt * BK);
        cp16(so + OFF_BH + toff + 16, whg + kt * BK + 8);
        cp16(so + OFF_BL + toff,      wlg + kt * BK);
        cp16(so + OFF_BL + toff + 16, wlg + kt * BK + 8);
        cp_commit();
    };

    cp_all(0, 0);
    cp_wait0();
    __syncthreads();

#pragma unroll 1
    for (int kt = 0; kt < NKT; ++kt) {
        const int cur = kt & 1;
        if (kt < NKT - 1) cp_all(kt + 1, cur ^ 1);
        mma_phase(g, g.sb + cur * STAGE_B, acc);
        cp_wait0();
        __syncthreads();
    }

    epilogue<true>(g, acc, bias, Y);
}

// ---------------------------------------------------------------------------
// Fused 4-way temporal attention, shuffle-free smem version.
// Writes bf16 hi/lo context planes (identical arithmetic to in-GEMM split).
// ---------------------------------------------------------------------------
__device__ __forceinline__ void attn_row(
    const float* __restrict__ A, const float* __restrict__ Bt,
    float* __restrict__ Prow, int t)
{
    float4 ar[8];
    const float4* ap = (const float4*)(A + t * RS);
#pragma unroll
    for (int q = 0; q < 8; ++q) ar[q] = ap[q];

    float s[T_];
#pragma unroll
    for (int j = 0; j < T_; ++j) {
        const float4* bp = (const float4*)(Bt + j * RS);
        float acc = 0.f;
#pragma unroll
        for (int q = 0; q < 8; ++q) {
            float4 b = bp[q];
            acc += ar[q].x * b.x + ar[q].y * b.y + ar[q].z * b.z + ar[q].w * b.w;
        }
        s[j] = acc;
    }
    float mx = s[0];
#pragma unroll
    for (int j = 1; j < T_; ++j) mx = fmaxf(mx, s[j]);
    float e[T_];
    float sum = 0.f;
#pragma unroll
    for (int j = 0; j < T_; ++j) { e[j] = __expf((s[j] - mx) * SCALE_); sum += e[j]; }
    const float inv = 1.0f / sum;
#pragma unroll
    for (int j = 0; j < T_; ++j) Prow[j] = e[j] * inv;
}

__global__ __launch_bounds__(256) void k_attn(
    const float* __restrict__ kj, const float* __restrict__ vfs)
{
    extern __shared__ float sm[];
    const int bn = blockIdx.x;
    const int h  = threadIdx.x >> 5;
    const int d  = threadIdx.x & 31;

    float* hs   = sm + h * HEAD_SM;
    float* tQf  = hs;
    float* tKf  = hs + 1 * TS;
    float* tQs  = hs + 2 * TS;
    float* tKs  = hs + 3 * TS;
    float* tQfs = hs + 4 * TS;
    float* P    = hs + 5 * TS;      // [4][12][PR]

    const size_t base = (size_t)bn * T_ * C_ + h * DK_ + d;

    const float* Qf = g_proj + 0 * MC_;
    const float* Kf = g_proj + 1 * MC_;
    const float* Vf = g_proj + 2 * MC_;
    const float* Qs = g_proj + 3 * MC_;
    const float* Ks = g_proj + 4 * MC_;
    const float* Vs = g_proj + 5 * MC_;

    float vf[T_], vs[T_];
#pragma unroll
    for (int t = 0; t < T_; ++t) {
        const size_t o = base + (size_t)t * C_;
        const float qf = Qf[o];
        const float kf = Kf[o];
        const float qs = Qs[o];
        const float ks = Ks[o];
        vf[t] = Vf[o];
        vs[t] = Vs[o];
        const float den = vfs[t] + 1e-5f;
        const float qfsv = kj[t] * (qs - qs * qs / den);
        tQf [t * RS + d] = qf;
        tKf [t * RS + d] = kf;
        tQs [t * RS + d] = qs;
        tKs [t * RS + d] = ks;
        tQfs[t * RS + d] = qfsv;
    }
    __syncwarp();

    {
        const int a0 = d / T_;          // 0..2
        const int t0 = d - a0 * T_;
        const float* Asel[4] = {tQf, tKf, tKs, tQs};
        const float* Bsel[4] = {tKf, tQfs, tQf, tKs};
        attn_row(Asel[a0], Bsel[a0], P + (a0 * T_ + t0) * PR, t0);
        if (d < 16) {
            const int r  = 32 + d;
            const int a1 = r / T_;      // 2..3
            const int t1 = r - a1 * T_;
            attn_row(Asel[a1], Bsel[a1], P + (a1 * T_ + t1) * PR, t1);
        }
    }
    __syncwarp();

#pragma unroll
    for (int a = 0; a < 4; ++a) {
        const float* vv = (a < 2) ? vf : vs;
        __nv_bfloat16* oh = g_ctx_h + (size_t)a * MC_ + base;
        __nv_bfloat16* ol = g_ctx_l + (size_t)a * MC_ + base;
#pragma unroll
        for (int t = 0; t < T_; ++t) {
            const float* pr = P + (a * T_ + t) * PR;
            float acc = 0.f;
#pragma unroll
            for (int j = 0; j < T_; ++j) acc += pr[j] * vv[j];
            const __nv_bfloat16 hv = __float2bfloat16(acc);
            oh[(size_t)t * C_] = hv;
            ol[(size_t)t * C_] = __float2bfloat16(acc - __bfloat162float(hv));
        }
    }
}

// ---------------------------------------------------------------------------
// Entry point
// ---------------------------------------------------------------------------
extern "C" void kernel_launch(void* const* d_in, const int* /*in_sizes*/,
                              int /*n_in*/, void* d_out, int /*out_size*/)
{
    const float* flow_q  = (const float*)d_in[0];
    const float* flow_k  = (const float*)d_in[1];
    const float* flow_v  = (const float*)d_in[2];
    const float* speed_q = (const float*)d_in[3];
    const float* speed_k = (const float*)d_in[4];
    const float* speed_v = (const float*)d_in[5];
    const float* w_fq  = (const float*)d_in[6];
    const float* w_fk  = (const float*)d_in[7];
    const float* w_fv  = (const float*)d_in[8];
    const float* w_sq  = (const float*)d_in[9];
    const float* w_sk  = (const float*)d_in[10];
    const float* w_sv  = (const float*)d_in[11];
    const float* w_out = (const float*)d_in[12];
    const float* b_out = (const float*)d_in[13];
    const float* kj    = (const float*)d_in[14];
    const float* vf_fs = (const float*)d_in[15];

    cudaFuncSetAttribute(k_attn, cudaFuncAttributeMaxDynamicSharedMemorySize,
                         SMEM_ATTN);
    cudaFuncSetAttribute(k_mma_proj, cudaFuncAttributeMaxDynamicSharedMemorySize,
                         SMEM_GEMM);
    cudaFuncSetAttribute(k_mma_out, cudaFuncAttributeMaxDynamicSharedMemorySize,
                         SMEM_GEMM);

    // 1. weight fp32 -> bf16 hi/lo (tiny)
    dim3 gcw((unsigned)(C_ * C_ / 4 / 256), 7);
    k_cvt_w<<<gcw, 256>>>(w_fq, w_fk, w_fv, w_sq, w_sk, w_sv, w_out);

    // 2. six input projections (R12 config: 2x4 warps, 2 CTAs/SM)
    dim3 gp(C_ / BN, M_ / BM, 6);   // (2, 384, 6)
    k_mma_proj<<<gp, 256, SMEM_GEMM>>>(flow_q, flow_k, flow_v,
                                       speed_q, speed_k, speed_v);

    // 3. fused attention (shuffle-free; emits bf16 hi/lo ctx planes)
    k_attn<<<B_ * N_, 256, SMEM_ATTN>>>(kj, vf_fs);

    // 4. four output projections (fully cp.async operand path)
    dim3 go(C_ / BN, M_ / BM, 4);   // (2, 384, 4)
    k_mma_out<<<go, 256, SMEM_GEMM>>>(b_out, (float*)d_out);
}